// round 10
// baseline (speedup 1.0000x reference)
#include <cuda_runtime.h>
#include <cstdint>
#include <cstddef>

#define TSTEPS 1024
#define BATCH  128
#define DIN    64
#define HH     512
#define NGRP   16        // row groups (8 rows each)
#define NC     8         // CTAs per cluster (64-col slices)
#define RG     8         // rows per group
#define CW     64        // cols per CTA slice
#define NTHR   512
#define HP     12        // float pitch per k-row
#define EPSF   1e-5f

#define NBUF   4
#define BUF_FL 4096                     // 64 rows x 64 cols floats = 16KB
#define BUF_BYTES 16384
#define CH_STEP 25
#define TOTBUF (CH_STEP * TSTEPS)

// ---- shared memory layout (float offsets) ----
#define OF_MBAR  0                          // 8 mbarriers (64B) + pad
#define OF_RING  16                         // NBUF * 4096 floats
#define OF_H0X   (OF_RING + NBUF * BUF_FL)
#define OF_H1X   (OF_H0X + 576 * HP)
#define OF_RED   (OF_H1X + 512 * HP)
#define OF_INBOX (OF_RED + 16 * 32 * 18)
#define OF_PART  (OF_INBOX + 2 * RG * HH)
#define OF_SG0   (OF_PART + 2 * NC * RG * 2)
#define OF_SB0   (OF_SG0 + HH)
#define OF_SG1   (OF_SB0 + HH)
#define OF_SB1   (OF_SG1 + HH)
#define OF_CB0   (OF_SB1 + HH)
#define OF_CB1   (OF_CB0 + CW)
#define OF_SP    (OF_CB1 + CW)
#define OF_SMU   (OF_SP + 32)
#define OF_SRS   (OF_SMU + RG)
#define SMEM_FL  (OF_SRS + RG)
#define SMEM_BYTES (SMEM_FL * 4)

typedef unsigned long long ull;

__device__ __forceinline__ ull ffma2(ull a, ull b, ull c) {
    ull d;
    asm("fma.rn.f32x2 %0, %1, %2, %3;" : "=l"(d) : "l"(a), "l"(b), "l"(c));
    return d;
}
__device__ __forceinline__ ull dup2(float f) {
    ull d;
    asm("mov.b64 %0, {%1, %1};" : "=l"(d) : "f"(f));
    return d;
}
__device__ __forceinline__ uint32_t smem_u32(const void* p) {
    uint32_t a;
    asm("{ .reg .u64 t; cvta.to.shared.u64 t, %1; cvt.u32.u64 %0, t; }" : "=r"(a) : "l"(p));
    return a;
}
__device__ __forceinline__ void st_cluster_v4(uint32_t laddr, int rank, float4 v) {
    uint32_t ra;
    asm volatile("mapa.shared::cluster.u32 %0, %1, %2;" : "=r"(ra) : "r"(laddr), "r"(rank));
    asm volatile("st.shared::cluster.v4.b32 [%0], {%1,%2,%3,%4};"
                 :: "r"(ra), "r"(__float_as_uint(v.x)), "r"(__float_as_uint(v.y)),
                    "r"(__float_as_uint(v.z)), "r"(__float_as_uint(v.w)) : "memory");
}
__device__ __forceinline__ void st_cluster_b64(uint32_t laddr, int rank, ull v) {
    uint32_t ra;
    asm volatile("mapa.shared::cluster.u32 %0, %1, %2;" : "=r"(ra) : "r"(laddr), "r"(rank));
    asm volatile("st.shared::cluster.b64 [%0], %1;" :: "r"(ra), "l"(v) : "memory");
}
__device__ __forceinline__ uint32_t ctarank() {
    uint32_t r;
    asm("mov.u32 %0, %%cluster_ctarank;" : "=r"(r));
    return r;
}
#define CL_ARRIVE() asm volatile("barrier.cluster.arrive.aligned;" ::: "memory")
#define CL_WAIT()   asm volatile("barrier.cluster.wait.aligned;" ::: "memory")

// ---- mbarrier primitives ----
__device__ __forceinline__ void mbar_init(uint32_t a, uint32_t cnt) {
    asm volatile("mbarrier.init.shared.b64 [%0], %1;" :: "r"(a), "r"(cnt) : "memory");
}
__device__ __forceinline__ void mbar_expect_tx(uint32_t a, uint32_t bytes) {
    asm volatile("mbarrier.arrive.expect_tx.shared.b64 _, [%0], %1;" :: "r"(a), "r"(bytes) : "memory");
}
__device__ __forceinline__ void mbar_arrive(uint32_t a) {
    asm volatile("mbarrier.arrive.shared.b64 _, [%0];" :: "r"(a) : "memory");
}
__device__ __forceinline__ void mbar_wait(uint32_t a, uint32_t parity) {
    uint32_t done;
    asm volatile(
        "{\n\t.reg .pred p;\n\t"
        "mbarrier.try_wait.parity.acquire.cta.shared::cta.b64 p, [%1], %2, 0x989680;\n\t"
        "selp.b32 %0, 1, 0, p;\n\t}"
        : "=r"(done) : "r"(a), "r"(parity) : "memory");
    while (!done) {
        asm volatile(
            "{\n\t.reg .pred p;\n\t"
            "mbarrier.try_wait.parity.acquire.cta.shared::cta.b64 p, [%1], %2, 0x989680;\n\t"
            "selp.b32 %0, 1, 0, p;\n\t}"
            : "=r"(done) : "r"(a), "r"(parity) : "memory");
    }
}
__device__ __forceinline__ void bulk256(uint32_t dst, const float* src, uint32_t mbar) {
    asm volatile(
        "cp.async.bulk.shared::cluster.global.mbarrier::complete_tx::bytes [%0], [%1], %2, [%3];"
        :: "r"(dst), "l"(src), "r"(256u), "r"(mbar) : "memory");
}

__global__ void __launch_bounds__(NTHR, 1) __cluster_dims__(NC, 1, 1)
rnn_bulk_kernel(
    const float* __restrict__ x,
    const float* __restrict__ Wi0, const float* __restrict__ bi0,
    const float* __restrict__ Wh0, const float* __restrict__ bh0,
    const float* __restrict__ g0,  const float* __restrict__ be0,
    const float* __restrict__ Wi1, const float* __restrict__ bi1,
    const float* __restrict__ Wh1, const float* __restrict__ bh1,
    const float* __restrict__ g1,  const float* __restrict__ be1,
    const float* __restrict__ Wfc, const float* __restrict__ bfc,
    float* __restrict__ out)
{
    extern __shared__ float sm[];
    float*  ring  = sm + OF_RING;
    float*  h0x   = sm + OF_H0X;
    float*  h1x   = sm + OF_H1X;
    float*  red   = sm + OF_RED;
    float*  inbox = sm + OF_INBOX;
    float2* part  = (float2*)(sm + OF_PART);
    float*  sg0   = sm + OF_SG0;  float* sb0 = sm + OF_SB0;
    float*  sg1   = sm + OF_SG1;  float* sb1 = sm + OF_SB1;
    float*  cb0   = sm + OF_CB0;  float* cb1 = sm + OF_CB1;
    float2* sp    = (float2*)(sm + OF_SP);
    float*  smu   = sm + OF_SMU;  float* srs = sm + OF_SRS;

    const int tid  = threadIdx.x;
    const int lane = tid & 31;
    const int p    = tid >> 5;          // warp = k-phase (16)
    const int cgo  = (lane & 15) * 4;   // col offset (4-col group)
    const int rqo  = (lane >> 4) * 4;   // row offset (4-row quad)
    const int rank = (int)ctarank();
    const int g    = blockIdx.x >> 3;
    const int c0   = rank * CW;
    const int row0 = g * RG;

    const uint32_t mbar_b  = smem_u32(sm + OF_MBAR);   // full[0..3] then empty[0..3]
    const uint32_t ring_b  = smem_u32(ring);
    const uint32_t inbox_b = smem_u32(inbox);
    const uint32_t part_b  = smem_u32(part);
#define MB_FULL(s)  (mbar_b + (uint32_t)(s) * 8u)
#define MB_EMPTY(s) (mbar_b + 32u + (uint32_t)(s) * 8u)

    // epilogue constants
    const int erow = tid >> 6;
    const int ecol = tid & 63;
    const float* rrd = red + (((erow >> 2) << 4) | (ecol >> 2)) * 18
                           + 4 * (erow & 3) + (ecol & 3);

    // ---- init ----
    sg0[tid] = g0[tid];  sb0[tid] = be0[tid];
    sg1[tid] = g1[tid];  sb1[tid] = be1[tid];
    if (tid < CW) {
        cb0[tid] = bi0[c0 + tid] + bh0[c0 + tid];
        cb1[tid] = bi1[c0 + tid] + bh1[c0 + tid];
    }
    for (int i = tid; i < 576 * HP; i += NTHR) h0x[i] = 0.f;
    for (int i = tid; i < 512 * HP; i += NTHR) h1x[i] = 0.f;
    if (tid == 0) {
#pragma unroll
        for (int s = 0; s < NBUF; ++s) {
            mbar_init(MB_FULL(s), 1);     // expect_tx arrival
            mbar_init(MB_EMPTY(s), 16);   // one arrive per warp
        }
    }
    __syncthreads();
    CL_ARRIVE();   // publishes init to peers; pairs with first E1 wait

    // ---- producer state (warp 0) ----
    int pb = 0, plocal = 0;
    if (p == 0) {
        // bootstrap: issue buffers 0..2 (no empty wait needed)
#pragma unroll
        for (int bb = 0; bb < 3; ++bb) {
            if (lane == 0) mbar_expect_tx(MB_FULL(bb), BUF_BYTES);
            __syncwarp();
            const float* base = (bb == 0) ? Wi0 : Wh0;
            int r0 = (bb == 0) ? 0 : (bb - 1) * 64;
            const float* src = base + (size_t)(r0 + 2 * lane) * HH + c0;
            uint32_t dst = ring_b + (uint32_t)(bb * BUF_BYTES + 2 * lane * 256);
            bulk256(dst, src, MB_FULL(bb));
            bulk256(dst + 256, src + HH, MB_FULL(bb));
        }
        pb = 3; plocal = 3;
    }

    int cb = 0;  // consumer buffer counter (uniform)

    // x prefetch
    const int xr = tid >> 6, xk = tid & 63;
    const float* xbase = x + (size_t)(row0 + xr) * TSTEPS * DIN + xk;
    float xreg = xbase[0];

    ull acc[8];

    for (int t = 0; t < TSTEPS; ++t) {
        h0x[xk * HP + xr] = xreg;
        __syncthreads();

#pragma unroll
        for (int q = 0; q < 8; ++q) acc[q] = 0ull;

        // ================== G0: 9 buffers (Wi0 + Wh0) ==================
#pragma unroll 1
        for (int bl = 0; bl < 9; ++bl) {
            if (p == 0 && pb < TOTBUF) {
                int s2 = pb & 3;
                if (pb >= 4) mbar_wait(MB_EMPTY(s2), ((pb - 4) >> 2) & 1);
                if (lane == 0) mbar_expect_tx(MB_FULL(s2), BUF_BYTES);
                __syncwarp();
                const float* base; int r0;
                if (plocal == 0)       { base = Wi0; r0 = 0; }
                else if (plocal <= 8)  { base = Wh0; r0 = (plocal - 1) * 64; }
                else if (plocal <= 16) { base = Wh1; r0 = (plocal - 9) * 64; }
                else                   { base = Wi1; r0 = (plocal - 17) * 64; }
                const float* src = base + (size_t)(r0 + 2 * lane) * HH + c0;
                uint32_t dst = ring_b + (uint32_t)(s2 * BUF_BYTES + 2 * lane * 256);
                bulk256(dst, src, MB_FULL(s2));
                bulk256(dst + 256, src + HH, MB_FULL(s2));
                ++pb; if (++plocal == CH_STEP) plocal = 0;
            }
            int s = cb & 3;
            mbar_wait(MB_FULL(s), (cb >> 2) & 1);
            const float* wbf = ring + s * BUF_FL + cgo;
            const float* hb  = (bl == 0) ? (h0x + rqo)
                                         : (h0x + (64 + (bl - 1) * 64) * HP + rqo);
#pragma unroll
            for (int j = 0; j < 4; ++j) {
                int rr = p + 16 * j;
                ulonglong2 w = *(const ulonglong2*)(wbf + rr * CW);
                float4 hv = *(const float4*)(hb + rr * HP);
                ull d0 = dup2(hv.x), d1 = dup2(hv.y), d2 = dup2(hv.z), d3 = dup2(hv.w);
                acc[0] = ffma2(d0, w.x, acc[0]); acc[1] = ffma2(d0, w.y, acc[1]);
                acc[2] = ffma2(d1, w.x, acc[2]); acc[3] = ffma2(d1, w.y, acc[3]);
                acc[4] = ffma2(d2, w.x, acc[4]); acc[5] = ffma2(d2, w.y, acc[5]);
                acc[6] = ffma2(d3, w.x, acc[6]); acc[7] = ffma2(d3, w.y, acc[7]);
            }
            if (lane == 0) mbar_arrive(MB_EMPTY(s));
            ++cb;
        }

        CL_WAIT();                       // E1(t-1): inbox[1], part[1] valid
        if (t > 0 && tid < 64) {
            int r = (tid >> 5) * 4 + ((tid & 31) >> 3);
            int s8 = tid & 7;
            float2 pv = part[(NC + s8) * RG + r];
#pragma unroll
            for (int o = 4; o; o >>= 1) {
                pv.x += __shfl_xor_sync(0xffffffffu, pv.x, o);
                pv.y += __shfl_xor_sync(0xffffffffu, pv.y, o);
            }
            if (s8 == 0) {
                float mu = pv.x * (1.f / HH);
                float var = pv.y * (1.f / HH) - mu * mu;
                smu[r] = mu; srs[r] = rsqrtf(var + EPSF);
            }
        }
        __syncthreads();
        if (t > 0) {                     // rebuild h1n(t-1)
            float gk = sg1[tid], bk = sb1[tid];
            const float* ib = inbox + RG * HH + tid;
            float4 u, v;
            u.x = (ib[0 * HH] - smu[0]) * srs[0] * gk + bk;
            u.y = (ib[1 * HH] - smu[1]) * srs[1] * gk + bk;
            u.z = (ib[2 * HH] - smu[2]) * srs[2] * gk + bk;
            u.w = (ib[3 * HH] - smu[3]) * srs[3] * gk + bk;
            v.x = (ib[4 * HH] - smu[4]) * srs[4] * gk + bk;
            v.y = (ib[5 * HH] - smu[5]) * srs[5] * gk + bk;
            v.z = (ib[6 * HH] - smu[6]) * srs[6] * gk + bk;
            v.w = (ib[7 * HH] - smu[7]) * srs[7] * gk + bk;
            *(float4*)(h1x + tid * HP) = u;
            *(float4*)(h1x + tid * HP + 4) = v;
        }
        {
            float* rw = red + p * 576 + lane * 18;
#pragma unroll
            for (int q = 0; q < 8; ++q) *(ull*)(rw + 2 * q) = acc[q];
        }
        __syncthreads();

        // ---- epilogue 0 ----
        {
            float z = 0.f;
#pragma unroll
            for (int i = 0; i < 16; ++i) z += rrd[i * 576];
            z += cb0[ecol];
            float cv = tanhf(z) + h0x[(64 + c0 + ecol) * HP + erow];
            inbox[erow * HH + c0 + ecol] = cv;
            float s = cv, q = cv * cv;
#pragma unroll
            for (int o = 16; o; o >>= 1) {
                s += __shfl_xor_sync(0xffffffffu, s, o);
                q += __shfl_xor_sync(0xffffffffu, q, o);
            }
            if (lane == 0) sp[p] = make_float2(s, q);
        }
        __syncthreads();
        if (tid < RG) {
            float2 a = sp[2 * tid], b = sp[2 * tid + 1];
            float2 pv = make_float2(a.x + b.x, a.y + b.y);
            part[rank * RG + tid] = pv;
            uint32_t off = (uint32_t)((rank * RG + tid) * 8);
            ull pbv = *(ull*)&pv;
#pragma unroll
            for (int d = 1; d < NC; ++d)
                st_cluster_b64(part_b + off, (rank + d) & (NC - 1), pbv);
        }
        if (tid < 128) {
            int rr = tid >> 4, cgi = tid & 15;
            int fo = rr * HH + c0 + 4 * cgi;
            float4 v = *(const float4*)(inbox + fo);
            uint32_t off = (uint32_t)(fo * 4);
#pragma unroll
            for (int d = 1; d < NC; ++d)
                st_cluster_v4(inbox_b + off, (rank + d) & (NC - 1), v);
        }
        CL_ARRIVE();                     // E0(t)

        // ================== G1a: 8 buffers (Wh1, uses h1n(t-1)) ==================
#pragma unroll
        for (int q = 0; q < 8; ++q) acc[q] = 0ull;
#pragma unroll 1
        for (int bl = 9; bl < 17; ++bl) {
            if (p == 0 && pb < TOTBUF) {
                int s2 = pb & 3;
                if (pb >= 4) mbar_wait(MB_EMPTY(s2), ((pb - 4) >> 2) & 1);
                if (lane == 0) mbar_expect_tx(MB_FULL(s2), BUF_BYTES);
                __syncwarp();
                const float* base; int r0;
                if (plocal == 0)       { base = Wi0; r0 = 0; }
                else if (plocal <= 8)  { base = Wh0; r0 = (plocal - 1) * 64; }
                else if (plocal <= 16) { base = Wh1; r0 = (plocal - 9) * 64; }
                else                   { base = Wi1; r0 = (plocal - 17) * 64; }
                const float* src = base + (size_t)(r0 + 2 * lane) * HH + c0;
                uint32_t dst = ring_b + (uint32_t)(s2 * BUF_BYTES + 2 * lane * 256);
                bulk256(dst, src, MB_FULL(s2));
                bulk256(dst + 256, src + HH, MB_FULL(s2));
                ++pb; if (++plocal == CH_STEP) plocal = 0;
            }
            int s = cb & 3;
            mbar_wait(MB_FULL(s), (cb >> 2) & 1);
            const float* wbf = ring + s * BUF_FL + cgo;
            const float* hb  = h1x + (bl - 9) * 64 * HP + rqo;
#pragma unroll
            for (int j = 0; j < 4; ++j) {
                int rr = p + 16 * j;
                ulonglong2 w = *(const ulonglong2*)(wbf + rr * CW);
                float4 hv = *(const float4*)(hb + rr * HP);
                ull d0 = dup2(hv.x), d1 = dup2(hv.y), d2 = dup2(hv.z), d3 = dup2(hv.w);
                acc[0] = ffma2(d0, w.x, acc[0]); acc[1] = ffma2(d0, w.y, acc[1]);
                acc[2] = ffma2(d1, w.x, acc[2]); acc[3] = ffma2(d1, w.y, acc[3]);
                acc[4] = ffma2(d2, w.x, acc[4]); acc[5] = ffma2(d2, w.y, acc[5]);
                acc[6] = ffma2(d3, w.x, acc[6]); acc[7] = ffma2(d3, w.y, acc[7]);
            }
            if (lane == 0) mbar_arrive(MB_EMPTY(s));
            ++cb;
        }

        CL_WAIT();                       // E0(t)
        if (tid < 64) {
            int r = (tid >> 5) * 4 + ((tid & 31) >> 3);
            int s8 = tid & 7;
            float2 pv = part[s8 * RG + r];
#pragma unroll
            for (int o = 4; o; o >>= 1) {
                pv.x += __shfl_xor_sync(0xffffffffu, pv.x, o);
                pv.y += __shfl_xor_sync(0xffffffffu, pv.y, o);
            }
            if (s8 == 0) {
                float mu = pv.x * (1.f / HH);
                float var = pv.y * (1.f / HH) - mu * mu;
                smu[r] = mu; srs[r] = rsqrtf(var + EPSF);
            }
        }
        __syncthreads();
        {                                // rebuild h0n(t)
            float gk = sg0[tid], bk = sb0[tid];
            const float* ib = inbox + tid;
            float4 u, v;
            u.x = (ib[0 * HH] - smu[0]) * srs[0] * gk + bk;
            u.y = (ib[1 * HH] - smu[1]) * srs[1] * gk + bk;
            u.z = (ib[2 * HH] - smu[2]) * srs[2] * gk + bk;
            u.w = (ib[3 * HH] - smu[3]) * srs[3] * gk + bk;
            v.x = (ib[4 * HH] - smu[4]) * srs[4] * gk + bk;
            v.y = (ib[5 * HH] - smu[5]) * srs[5] * gk + bk;
            v.z = (ib[6 * HH] - smu[6]) * srs[6] * gk + bk;
            v.w = (ib[7 * HH] - smu[7]) * srs[7] * gk + bk;
            *(float4*)(h0x + (64 + tid) * HP) = u;
            *(float4*)(h0x + (64 + tid) * HP + 4) = v;
        }
        __syncthreads();

        // ================== G1b: 8 buffers (Wi1, uses h0n(t)) ==================
#pragma unroll 1
        for (int bl = 17; bl < 25; ++bl) {
            if (p == 0 && pb < TOTBUF) {
                int s2 = pb & 3;
                if (pb >= 4) mbar_wait(MB_EMPTY(s2), ((pb - 4) >> 2) & 1);
                if (lane == 0) mbar_expect_tx(MB_FULL(s2), BUF_BYTES);
                __syncwarp();
                const float* base; int r0;
                if (plocal == 0)       { base = Wi0; r0 = 0; }
                else if (plocal <= 8)  { base = Wh0; r0 = (plocal - 1) * 64; }
                else if (plocal <= 16) { base = Wh1; r0 = (plocal - 9) * 64; }
                else                   { base = Wi1; r0 = (plocal - 17) * 64; }
                const float* src = base + (size_t)(r0 + 2 * lane) * HH + c0;
                uint32_t dst = ring_b + (uint32_t)(s2 * BUF_BYTES + 2 * lane * 256);
                bulk256(dst, src, MB_FULL(s2));
                bulk256(dst + 256, src + HH, MB_FULL(s2));
                ++pb; if (++plocal == CH_STEP) plocal = 0;
            }
            int s = cb & 3;
            mbar_wait(MB_FULL(s), (cb >> 2) & 1);
            const float* wbf = ring + s * BUF_FL + cgo;
            const float* hb  = h0x + (64 + (bl - 17) * 64) * HP + rqo;
#pragma unroll
            for (int j = 0; j < 4; ++j) {
                int rr = p + 16 * j;
                ulonglong2 w = *(const ulonglong2*)(wbf + rr * CW);
                float4 hv = *(const float4*)(hb + rr * HP);
                ull d0 = dup2(hv.x), d1 = dup2(hv.y), d2 = dup2(hv.z), d3 = dup2(hv.w);
                acc[0] = ffma2(d0, w.x, acc[0]); acc[1] = ffma2(d0, w.y, acc[1]);
                acc[2] = ffma2(d1, w.x, acc[2]); acc[3] = ffma2(d1, w.y, acc[3]);
                acc[4] = ffma2(d2, w.x, acc[4]); acc[5] = ffma2(d2, w.y, acc[5]);
                acc[6] = ffma2(d3, w.x, acc[6]); acc[7] = ffma2(d3, w.y, acc[7]);
            }
            if (lane == 0) mbar_arrive(MB_EMPTY(s));
            ++cb;
        }
        if (t + 1 < TSTEPS) xreg = xbase[(size_t)(t + 1) * DIN];
        {
            float* rw = red + p * 576 + lane * 18;
#pragma unroll
            for (int q = 0; q < 8; ++q) *(ull*)(rw + 2 * q) = acc[q];
        }
        __syncthreads();

        // ---- epilogue 1 ----
        {
            float z = 0.f;
#pragma unroll
            for (int i = 0; i < 16; ++i) z += rrd[i * 576];
            z += cb1[ecol];
            float cv = tanhf(z) + h1x[(c0 + ecol) * HP + erow];
            inbox[RG * HH + erow * HH + c0 + ecol] = cv;
            float s = cv, q = cv * cv;
#pragma unroll
            for (int o = 16; o; o >>= 1) {
                s += __shfl_xor_sync(0xffffffffu, s, o);
                q += __shfl_xor_sync(0xffffffffu, q, o);
            }
            if (lane == 0) sp[p] = make_float2(s, q);
        }
        __syncthreads();
        if (tid < RG) {
            float2 a = sp[2 * tid], b = sp[2 * tid + 1];
            float2 pv = make_float2(a.x + b.x, a.y + b.y);
            part[(NC + rank) * RG + tid] = pv;
            uint32_t off = (uint32_t)(((NC + rank) * RG + tid) * 8);
            ull pbv = *(ull*)&pv;
#pragma unroll
            for (int d = 1; d < NC; ++d)
                st_cluster_b64(part_b + off, (rank + d) & (NC - 1), pbv);
        }
        if (tid < 128) {
            int rr = tid >> 4, cgi = tid & 15;
            int fo = RG * HH + rr * HH + c0 + 4 * cgi;
            float4 v = *(const float4*)(inbox + fo);
            uint32_t off = (uint32_t)(fo * 4);
#pragma unroll
            for (int d = 1; d < NC; ++d)
                st_cluster_v4(inbox_b + off, (rank + d) & (NC - 1), v);
        }
        CL_ARRIVE();                     // E1(t)
    }

    // ---- final: wait E1(T-1), rebuild h1n, output head ----
    CL_WAIT();
    if (tid < 64) {
        int r = (tid >> 5) * 4 + ((tid & 31) >> 3);
        int s8 = tid & 7;
        float2 pv = part[(NC + s8) * RG + r];
#pragma unroll
        for (int o = 4; o; o >>= 1) {
            pv.x += __shfl_xor_sync(0xffffffffu, pv.x, o);
            pv.y += __shfl_xor_sync(0xffffffffu, pv.y, o);
        }
        if (s8 == 0) {
            float mu = pv.x * (1.f / HH);
            float var = pv.y * (1.f / HH) - mu * mu;
            smu[r] = mu; srs[r] = rsqrtf(var + EPSF);
        }
    }
    __syncthreads();
    {
        float gk = sg1[tid], bk = sb1[tid];
        const float* ib = inbox + RG * HH + tid;
#pragma unroll
        for (int r = 0; r < RG; ++r)
            h1x[tid * HP + r] = (ib[r * HH] - smu[r]) * srs[r] * gk + bk;
    }
    __syncthreads();
    if (rank == 0 && p < RG) {
        float v = 0.f;
#pragma unroll
        for (int m = 0; m < 16; ++m) {
            int k = lane + 32 * m;
            v += h1x[k * HP + p] * Wfc[k];
        }
#pragma unroll
        for (int o = 16; o; o >>= 1) v += __shfl_xor_sync(0xffffffffu, v, o);
        if (lane == 0) out[row0 + p] = v + bfc[0];
    }
}

extern "C" void kernel_launch(void* const* d_in, const int* in_sizes, int n_in,
                              void* d_out, int out_size) {
    (void)in_sizes; (void)n_in; (void)out_size;
    const float* x   = (const float*)d_in[0];
    const float* Wi0 = (const float*)d_in[1];
    const float* bi0 = (const float*)d_in[2];
    const float* Wh0 = (const float*)d_in[3];
    const float* bh0 = (const float*)d_in[4];
    const float* g0  = (const float*)d_in[5];
    const float* be0 = (const float*)d_in[6];
    const float* Wi1 = (const float*)d_in[7];
    const float* bi1 = (const float*)d_in[8];
    const float* Wh1 = (const float*)d_in[9];
    const float* bh1 = (const float*)d_in[10];
    const float* g1  = (const float*)d_in[11];
    const float* be1 = (const float*)d_in[12];
    const float* Wfc = (const float*)d_in[13];
    const float* bfc = (const float*)d_in[14];

    static int inited = 0;
    if (!inited) {
        cudaFuncSetAttribute(rnn_bulk_kernel,
                             cudaFuncAttributeMaxDynamicSharedMemorySize, SMEM_BYTES);
        inited = 1;
    }
    rnn_bulk_kernel<<<NGRP * NC, NTHR, SMEM_BYTES>>>(
        x, Wi0, bi0, Wh0, bh0, g0, be0,
        Wi1, bi1, Wh1, bh1, g1, be1,
        Wfc, bfc, (float*)d_out);
}

// round 11
// speedup vs baseline: 2.4672x; 2.4672x over previous
#include <cuda_runtime.h>
#include <cstdint>
#include <cstddef>

#define TSTEPS 1024
#define BATCH  128
#define DIN    64
#define HH     512
#define NGRP   16        // row groups (8 rows each)
#define NC     8         // CTAs per cluster (64-col slices)
#define RG     8         // rows per group
#define CW     64        // cols per CTA slice
#define NTHR   512
#define HP     12        // float pitch per k-row
#define EPSF   1e-5f

#define NBUF     5
#define BUF_FL   4096                   // 64 rows x 64 cols floats = 16KB
#define BUF_BYTES 16384
#define CH_STEP  25
#define TOTCHK   (CH_STEP * TSTEPS)

// ---- shared memory layout (float offsets) ----
#define OF_RING  0
#define OF_H0X   (OF_RING + NBUF * BUF_FL)  // [576][HP]: rows 0..63 = x_t, 64..575 = h0n
#define OF_H1X   (OF_H0X + 576 * HP)        // [512][HP]
#define OF_RED   (OF_H1X + 512 * HP)        // [16][32][18]
#define OF_INBOX (OF_RED + 16 * 32 * 18)    // [2][RG][HH]
#define OF_PART  (OF_INBOX + 2 * RG * HH)   // [2][NC][RG] float2
#define OF_SG0   (OF_PART + 2 * NC * RG * 2)
#define OF_SB0   (OF_SG0 + HH)
#define OF_SG1   (OF_SB0 + HH)
#define OF_SB1   (OF_SG1 + HH)
#define OF_CB0   (OF_SB1 + HH)
#define OF_CB1   (OF_CB0 + CW)
#define OF_SP    (OF_CB1 + CW)              // [16] float2
#define OF_SMU   (OF_SP + 32)
#define OF_SRS   (OF_SMU + RG)
#define SMEM_FL  (OF_SRS + RG)
#define SMEM_BYTES (SMEM_FL * 4)

typedef unsigned long long ull;

__device__ __forceinline__ ull ffma2(ull a, ull b, ull c) {
    ull d;
    asm("fma.rn.f32x2 %0, %1, %2, %3;" : "=l"(d) : "l"(a), "l"(b), "l"(c));
    return d;
}
__device__ __forceinline__ ull dup2(float f) {
    ull d;
    asm("mov.b64 %0, {%1, %1};" : "=l"(d) : "f"(f));
    return d;
}
__device__ __forceinline__ uint32_t smem_u32(const void* p) {
    uint32_t a;
    asm("{ .reg .u64 t; cvta.to.shared.u64 t, %1; cvt.u32.u64 %0, t; }" : "=r"(a) : "l"(p));
    return a;
}
__device__ __forceinline__ void cp_async16(uint32_t dst, const float* src) {
    asm volatile("cp.async.cg.shared.global [%0], [%1], 16;" :: "r"(dst), "l"(src) : "memory");
}
__device__ __forceinline__ void st_cluster_v4(uint32_t laddr, int rank, float4 v) {
    uint32_t ra;
    asm volatile("mapa.shared::cluster.u32 %0, %1, %2;" : "=r"(ra) : "r"(laddr), "r"(rank));
    asm volatile("st.shared::cluster.v4.b32 [%0], {%1,%2,%3,%4};"
                 :: "r"(ra), "r"(__float_as_uint(v.x)), "r"(__float_as_uint(v.y)),
                    "r"(__float_as_uint(v.z)), "r"(__float_as_uint(v.w)) : "memory");
}
__device__ __forceinline__ void st_cluster_b64(uint32_t laddr, int rank, ull v) {
    uint32_t ra;
    asm volatile("mapa.shared::cluster.u32 %0, %1, %2;" : "=r"(ra) : "r"(laddr), "r"(rank));
    asm volatile("st.shared::cluster.b64 [%0], %1;" :: "r"(ra), "l"(v) : "memory");
}
__device__ __forceinline__ uint32_t ctarank() {
    uint32_t r;
    asm("mov.u32 %0, %%cluster_ctarank;" : "=r"(r));
    return r;
}
#define CL_ARRIVE() asm volatile("barrier.cluster.arrive.aligned;" ::: "memory")
#define CL_WAIT()   asm volatile("barrier.cluster.wait.aligned;" ::: "memory")
#define CP_COMMIT() asm volatile("cp.async.commit_group;" ::: "memory")
#define CP_WAIT3()  asm volatile("cp.async.wait_group 3;" ::: "memory")

__global__ void __launch_bounds__(NTHR, 1) __cluster_dims__(NC, 1, 1)
rnn_ring_kernel(
    const float* __restrict__ x,
    const float* __restrict__ Wi0, const float* __restrict__ bi0,
    const float* __restrict__ Wh0, const float* __restrict__ bh0,
    const float* __restrict__ g0,  const float* __restrict__ be0,
    const float* __restrict__ Wi1, const float* __restrict__ bi1,
    const float* __restrict__ Wh1, const float* __restrict__ bh1,
    const float* __restrict__ g1,  const float* __restrict__ be1,
    const float* __restrict__ Wfc, const float* __restrict__ bfc,
    float* __restrict__ out)
{
    extern __shared__ float sm[];
    float*  ring  = sm + OF_RING;
    float*  h0x   = sm + OF_H0X;
    float*  h1x   = sm + OF_H1X;
    float*  red   = sm + OF_RED;
    float*  inbox = sm + OF_INBOX;
    float2* part  = (float2*)(sm + OF_PART);
    float*  sg0   = sm + OF_SG0;  float* sb0 = sm + OF_SB0;
    float*  sg1   = sm + OF_SG1;  float* sb1 = sm + OF_SB1;
    float*  cb0   = sm + OF_CB0;  float* cb1 = sm + OF_CB1;
    float2* sp    = (float2*)(sm + OF_SP);
    float*  smu   = sm + OF_SMU;  float* srs = sm + OF_SRS;

    const int tid  = threadIdx.x;
    const int lane = tid & 31;
    const int p    = tid >> 5;          // warp = k-phase (16)
    const int cgo  = (lane & 15) * 4;   // col offset (4-col group)
    const int rqo  = (lane >> 4) * 4;   // row offset (4-row quad)
    const int rank = (int)ctarank();
    const int g    = blockIdx.x >> 3;
    const int c0   = rank * CW;
    const int row0 = g * RG;

    const uint32_t ring_b  = smem_u32(ring);
    const uint32_t inbox_b = smem_u32(inbox);
    const uint32_t part_b  = smem_u32(part);

    // epilogue constants
    const int erow = tid >> 6;
    const int ecol = tid & 63;
    const float* rrd = red + (((erow >> 2) << 4) | (ecol >> 2)) * 18
                           + 4 * (erow & 3) + (ecol & 3);

    // issue-side per-thread source offset pieces (16KB chunk = 1024 16B segs; thread
    // covers segs tid and tid+512 => rows (tid>>4) and (tid>>4)+32, colseg tid&15)
    const int irow = tid >> 4;
    const int icol = (tid & 15) * 4;
    const uint32_t idst0 = (uint32_t)tid * 16u;
    const uint32_t idst1 = (uint32_t)(tid + 512) * 16u;

    // ---- init ----
    sg0[tid] = g0[tid];  sb0[tid] = be0[tid];
    sg1[tid] = g1[tid];  sb1[tid] = be1[tid];
    if (tid < CW) {
        cb0[tid] = bi0[c0 + tid] + bh0[c0 + tid];
        cb1[tid] = bi1[c0 + tid] + bh1[c0 + tid];
    }
    for (int i = tid; i < 576 * HP; i += NTHR) h0x[i] = 0.f;
    for (int i = tid; i < 512 * HP; i += NTHR) h1x[i] = 0.f;
    __syncthreads();
    CL_ARRIVE();   // publishes init; pairs with first E1 wait

    // ---- cp.async pipeline bootstrap: issue chunks 0..3 (one commit group each) ----
    // chunk s in step order: 0 = Wi0[0:64), 1..8 = Wh0, 9..16 = Wh1, 17..24 = Wi1
    int issued = 0, ploc = 0, islot = 0;
#pragma unroll
    for (int bb = 0; bb < 4; ++bb) {
        const float* base = (bb == 0) ? Wi0 : Wh0;
        int r0 = (bb == 0) ? 0 : (bb - 1) * 64;
        const float* s1 = base + (size_t)(r0 + irow) * HH + c0 + icol;
        uint32_t db = ring_b + (uint32_t)(bb * BUF_BYTES);
        cp_async16(db + idst0, s1);
        cp_async16(db + idst1, s1 + (size_t)32 * HH);
        CP_COMMIT();
    }
    issued = 4; ploc = 4; islot = 4;
    int cslot = 0;

    // x prefetch
    const int xr = tid >> 6, xk = tid & 63;
    const float* xbase = x + (size_t)(row0 + xr) * TSTEPS * DIN + xk;
    float xreg = xbase[0];

    ull acc[8];

    for (int t = 0; t < TSTEPS; ++t) {
        h0x[xk * HP + xr] = xreg;   // chunk-0's sync publishes this

#pragma unroll
        for (int q = 0; q < 8; ++q) acc[q] = 0ull;

        // ================== 25 chunks, interleaved with exchanges ==================
#pragma unroll 1
        for (int bl = 0; bl < CH_STEP; ++bl) {
            // -------- stage-boundary exchange work (before consuming chunk bl) -----
            if (bl == 9) {
                CL_WAIT();                       // E1(t-1)
                if (t > 0 && tid < 64) {
                    int r = (tid >> 5) * 4 + ((tid & 31) >> 3);
                    int s8 = tid & 7;
                    float2 pv = part[(NC + s8) * RG + r];
#pragma unroll
                    for (int o = 4; o; o >>= 1) {
                        pv.x += __shfl_xor_sync(0xffffffffu, pv.x, o);
                        pv.y += __shfl_xor_sync(0xffffffffu, pv.y, o);
                    }
                    if (s8 == 0) {
                        float mu = pv.x * (1.f / HH);
                        float var = pv.y * (1.f / HH) - mu * mu;
                        smu[r] = mu; srs[r] = rsqrtf(var + EPSF);
                    }
                }
                __syncthreads();
                if (t > 0) {                     // rebuild h1n(t-1)
                    float gk = sg1[tid], bk = sb1[tid];
                    const float* ib = inbox + RG * HH + tid;
                    float4 u, v;
                    u.x = (ib[0 * HH] - smu[0]) * srs[0] * gk + bk;
                    u.y = (ib[1 * HH] - smu[1]) * srs[1] * gk + bk;
                    u.z = (ib[2 * HH] - smu[2]) * srs[2] * gk + bk;
                    u.w = (ib[3 * HH] - smu[3]) * srs[3] * gk + bk;
                    v.x = (ib[4 * HH] - smu[4]) * srs[4] * gk + bk;
                    v.y = (ib[5 * HH] - smu[5]) * srs[5] * gk + bk;
                    v.z = (ib[6 * HH] - smu[6]) * srs[6] * gk + bk;
                    v.w = (ib[7 * HH] - smu[7]) * srs[7] * gk + bk;
                    *(float4*)(h1x + tid * HP) = u;
                    *(float4*)(h1x + tid * HP + 4) = v;
                }
                {
                    float* rw = red + p * 576 + lane * 18;
#pragma unroll
                    for (int q = 0; q < 8; ++q) *(ull*)(rw + 2 * q) = acc[q];
                }
                __syncthreads();
                // ---- epilogue 0 ----
                {
                    float z = 0.f;
#pragma unroll
                    for (int i = 0; i < 16; ++i) z += rrd[i * 576];
                    z += cb0[ecol];
                    float cv = tanhf(z) + h0x[(64 + c0 + ecol) * HP + erow];
                    inbox[erow * HH + c0 + ecol] = cv;
                    float s = cv, q = cv * cv;
#pragma unroll
                    for (int o = 16; o; o >>= 1) {
                        s += __shfl_xor_sync(0xffffffffu, s, o);
                        q += __shfl_xor_sync(0xffffffffu, q, o);
                    }
                    if (lane == 0) sp[p] = make_float2(s, q);
                }
                __syncthreads();
                if (tid < RG) {
                    float2 a = sp[2 * tid], b = sp[2 * tid + 1];
                    float2 pv = make_float2(a.x + b.x, a.y + b.y);
                    part[rank * RG + tid] = pv;
                    uint32_t off = (uint32_t)((rank * RG + tid) * 8);
                    ull pbv = *(ull*)&pv;
#pragma unroll
                    for (int d = 1; d < NC; ++d)
                        st_cluster_b64(part_b + off, (rank + d) & (NC - 1), pbv);
                }
                if (tid < 128) {
                    int rr = tid >> 4, cgi = tid & 15;
                    int fo = rr * HH + c0 + 4 * cgi;
                    float4 v = *(const float4*)(inbox + fo);
                    uint32_t off = (uint32_t)(fo * 4);
#pragma unroll
                    for (int d = 1; d < NC; ++d)
                        st_cluster_v4(inbox_b + off, (rank + d) & (NC - 1), v);
                }
                CL_ARRIVE();                     // E0(t)
#pragma unroll
                for (int q = 0; q < 8; ++q) acc[q] = 0ull;
            }
            if (bl == 17) {
                CL_WAIT();                       // E0(t)
                if (tid < 64) {
                    int r = (tid >> 5) * 4 + ((tid & 31) >> 3);
                    int s8 = tid & 7;
                    float2 pv = part[s8 * RG + r];
#pragma unroll
                    for (int o = 4; o; o >>= 1) {
                        pv.x += __shfl_xor_sync(0xffffffffu, pv.x, o);
                        pv.y += __shfl_xor_sync(0xffffffffu, pv.y, o);
                    }
                    if (s8 == 0) {
                        float mu = pv.x * (1.f / HH);
                        float var = pv.y * (1.f / HH) - mu * mu;
                        smu[r] = mu; srs[r] = rsqrtf(var + EPSF);
                    }
                }
                __syncthreads();
                {                                // rebuild h0n(t)
                    float gk = sg0[tid], bk = sb0[tid];
                    const float* ib = inbox + tid;
                    float4 u, v;
                    u.x = (ib[0 * HH] - smu[0]) * srs[0] * gk + bk;
                    u.y = (ib[1 * HH] - smu[1]) * srs[1] * gk + bk;
                    u.z = (ib[2 * HH] - smu[2]) * srs[2] * gk + bk;
                    u.w = (ib[3 * HH] - smu[3]) * srs[3] * gk + bk;
                    v.x = (ib[4 * HH] - smu[4]) * srs[4] * gk + bk;
                    v.y = (ib[5 * HH] - smu[5]) * srs[5] * gk + bk;
                    v.z = (ib[6 * HH] - smu[6]) * srs[6] * gk + bk;
                    v.w = (ib[7 * HH] - smu[7]) * srs[7] * gk + bk;
                    *(float4*)(h0x + (64 + tid) * HP) = u;
                    *(float4*)(h0x + (64 + tid) * HP + 4) = v;
                }
                __syncthreads();
            }

            // -------- pipelined chunk: wait, publish, issue ahead, compute --------
            CP_WAIT3();
            __syncthreads();        // chunk bl visible; everyone done with bl-1

            if (issued < TOTCHK) {  // issue chunk (global) bl+4 into slot islot
                const float* base; int r0;
                int s = ploc;
                if (s == 0)       { base = Wi0; r0 = 0; }
                else if (s <= 8)  { base = Wh0; r0 = (s - 1) * 64; }
                else if (s <= 16) { base = Wh1; r0 = (s - 9) * 64; }
                else              { base = Wi1; r0 = (s - 17) * 64; }
                const float* s1 = base + (size_t)(r0 + irow) * HH + c0 + icol;
                uint32_t db = ring_b + (uint32_t)(islot * BUF_BYTES);
                cp_async16(db + idst0, s1);
                cp_async16(db + idst1, s1 + (size_t)32 * HH);
                ++issued;
                if (++ploc == CH_STEP) ploc = 0;
                if (++islot == NBUF) islot = 0;
            }
            CP_COMMIT();            // unconditional: keeps group counting aligned

            // compute chunk bl from slot cslot
            const float* hbase;
            if (bl == 0)        hbase = h0x;                            // x rows
            else if (bl <= 8)   hbase = h0x + (64 + (bl - 1) * 64) * HP; // h0n(t-1)/h0n(t)
            else if (bl <= 16)  hbase = h1x + (bl - 9) * 64 * HP;        // h1n(t-1)
            else                hbase = h0x + (64 + (bl - 17) * 64) * HP; // h0n(t)
            const float* wt = ring + cslot * BUF_FL + p * CW + cgo;
            const float* hp = hbase + p * HP + rqo;
#pragma unroll
            for (int i = 0; i < 4; ++i) {
                ulonglong2 w = *(const ulonglong2*)(wt + i * 16 * CW);
                float4 hv = *(const float4*)(hp + i * 16 * HP);
                ull d0 = dup2(hv.x), d1 = dup2(hv.y), d2 = dup2(hv.z), d3 = dup2(hv.w);
                acc[0] = ffma2(d0, w.x, acc[0]); acc[1] = ffma2(d0, w.y, acc[1]);
                acc[2] = ffma2(d1, w.x, acc[2]); acc[3] = ffma2(d1, w.y, acc[3]);
                acc[4] = ffma2(d2, w.x, acc[4]); acc[5] = ffma2(d2, w.y, acc[5]);
                acc[6] = ffma2(d3, w.x, acc[6]); acc[7] = ffma2(d3, w.y, acc[7]);
            }
            if (++cslot == NBUF) cslot = 0;
        }

        // ---- end of step: epilogue 1 + E1 broadcast ----
        if (t + 1 < TSTEPS) xreg = xbase[(size_t)(t + 1) * DIN];
        {
            float* rw = red + p * 576 + lane * 18;
#pragma unroll
            for (int q = 0; q < 8; ++q) *(ull*)(rw + 2 * q) = acc[q];
        }
        __syncthreads();
        {
            float z = 0.f;
#pragma unroll
            for (int i = 0; i < 16; ++i) z += rrd[i * 576];
            z += cb1[ecol];
            float cv = tanhf(z) + h1x[(c0 + ecol) * HP + erow];
            inbox[RG * HH + erow * HH + c0 + ecol] = cv;
            float s = cv, q = cv * cv;
#pragma unroll
            for (int o = 16; o; o >>= 1) {
                s += __shfl_xor_sync(0xffffffffu, s, o);
                q += __shfl_xor_sync(0xffffffffu, q, o);
            }
            if (lane == 0) sp[p] = make_float2(s, q);
        }
        __syncthreads();
        if (tid < RG) {
            float2 a = sp[2 * tid], b = sp[2 * tid + 1];
            float2 pv = make_float2(a.x + b.x, a.y + b.y);
            part[(NC + rank) * RG + tid] = pv;
            uint32_t off = (uint32_t)(((NC + rank) * RG + tid) * 8);
            ull pbv = *(ull*)&pv;
#pragma unroll
            for (int d = 1; d < NC; ++d)
                st_cluster_b64(part_b + off, (rank + d) & (NC - 1), pbv);
        }
        if (tid < 128) {
            int rr = tid >> 4, cgi = tid & 15;
            int fo = RG * HH + rr * HH + c0 + 4 * cgi;
            float4 v = *(const float4*)(inbox + fo);
            uint32_t off = (uint32_t)(fo * 4);
#pragma unroll
            for (int d = 1; d < NC; ++d)
                st_cluster_v4(inbox_b + off, (rank + d) & (NC - 1), v);
        }
        CL_ARRIVE();                     // E1(t)
    }

    // ---- final: wait E1(T-1), rebuild h1n, output head ----
    CL_WAIT();
    if (tid < 64) {
        int r = (tid >> 5) * 4 + ((tid & 31) >> 3);
        int s8 = tid & 7;
        float2 pv = part[(NC + s8) * RG + r];
#pragma unroll
        for (int o = 4; o; o >>= 1) {
            pv.x += __shfl_xor_sync(0xffffffffu, pv.x, o);
            pv.y += __shfl_xor_sync(0xffffffffu, pv.y, o);
        }
        if (s8 == 0) {
            float mu = pv.x * (1.f / HH);
            float var = pv.y * (1.f / HH) - mu * mu;
            smu[r] = mu; srs[r] = rsqrtf(var + EPSF);
        }
    }
    __syncthreads();
    {
        float gk = sg1[tid], bk = sb1[tid];
        const float* ib = inbox + RG * HH + tid;
#pragma unroll
        for (int r = 0; r < RG; ++r)
            h1x[tid * HP + r] = (ib[r * HH] - smu[r]) * srs[r] * gk + bk;
    }
    __syncthreads();
    if (rank == 0 && p < RG) {
        float v = 0.f;
#pragma unroll
        for (int m = 0; m < 16; ++m) {
            int k = lane + 32 * m;
            v += h1x[k * HP + p] * Wfc[k];
        }
#pragma unroll
        for (int o = 16; o; o >>= 1) v += __shfl_xor_sync(0xffffffffu, v, o);
        if (lane == 0) out[row0 + p] = v + bfc[0];
    }
}

extern "C" void kernel_launch(void* const* d_in, const int* in_sizes, int n_in,
                              void* d_out, int out_size) {
    (void)in_sizes; (void)n_in; (void)out_size;
    const float* x   = (const float*)d_in[0];
    const float* Wi0 = (const float*)d_in[1];
    const float* bi0 = (const float*)d_in[2];
    const float* Wh0 = (const float*)d_in[3];
    const float* bh0 = (const float*)d_in[4];
    const float* g0  = (const float*)d_in[5];
    const float* be0 = (const float*)d_in[6];
    const float* Wi1 = (const float*)d_in[7];
    const float* bi1 = (const float*)d_in[8];
    const float* Wh1 = (const float*)d_in[9];
    const float* bh1 = (const float*)d_in[10];
    const float* g1  = (const float*)d_in[11];
    const float* be1 = (const float*)d_in[12];
    const float* Wfc = (const float*)d_in[13];
    const float* bfc = (const float*)d_in[14];

    static int inited = 0;
    if (!inited) {
        cudaFuncSetAttribute(rnn_ring_kernel,
                             cudaFuncAttributeMaxDynamicSharedMemorySize, SMEM_BYTES);
        inited = 1;
    }
    rnn_ring_kernel<<<NGRP * NC, NTHR, SMEM_BYTES>>>(
        x, Wi0, bi0, Wh0, bh0, g0, be0,
        Wi1, bi1, Wh1, bh1, g1, be1,
        Wfc, bfc, (float*)d_out);
}

// round 12
// speedup vs baseline: 9.6481x; 3.9105x over previous
#include <cuda_runtime.h>
#include <cstdint>
#include <cstddef>

#define TSTEPS 1024
#define BATCH  128
#define DIN    64
#define HH     512
#define NGRP   32        // row groups (4 rows each)
#define NC     8         // CTAs per cluster (64-col slices)
#define RG     4         // rows per group
#define CW     64        // cols per CTA slice
#define NTHR   256
#define NW     8         // warps = k-phases
#define HP     6         // float pitch per k-row (4 rows + 2 pad, 8B-aligned rows)
#define EPSF   1e-5f

// ---- shared memory layout (float offsets) ----
#define OF_H0X   0                         // [576][HP]: rows 0..63 = x_t, 64..575 = h0n
#define OF_H1X   (OF_H0X + 576 * HP)       // [512][HP]
#define OF_RED   (OF_H1X + 512 * HP)       // [8][32][10]
#define OF_INBOX (OF_RED + 8 * 32 * 10)    // [2][RG][HH]
#define OF_PART  (OF_INBOX + 2 * RG * HH)  // [2][NC][RG] float2
#define OF_SG0   (OF_PART + 2 * NC * RG * 2)
#define OF_SB0   (OF_SG0 + HH)
#define OF_SG1   (OF_SB0 + HH)
#define OF_SB1   (OF_SG1 + HH)
#define OF_CB0   (OF_SB1 + HH)
#define OF_CB1   (OF_CB0 + CW)
#define OF_SP    (OF_CB1 + CW)             // [8] float2 (per-warp LN partials)
#define OF_SMU   (OF_SP + 16)
#define OF_SRS   (OF_SMU + RG)
#define SMEM_FL  (OF_SRS + RG)
#define SMEM_BYTES (SMEM_FL * 4)

typedef unsigned long long ull;

__device__ __forceinline__ ull ffma2(ull a, ull b, ull c) {
    ull d;
    asm("fma.rn.f32x2 %0, %1, %2, %3;" : "=l"(d) : "l"(a), "l"(b), "l"(c));
    return d;
}
__device__ __forceinline__ ull dup2(float f) {
    ull d;
    asm("mov.b64 %0, {%1, %1};" : "=l"(d) : "f"(f));
    return d;
}
__device__ __forceinline__ uint32_t smem_u32(const void* p) {
    uint32_t a;
    asm("{ .reg .u64 t; cvta.to.shared.u64 t, %1; cvt.u32.u64 %0, t; }" : "=r"(a) : "l"(p));
    return a;
}
__device__ __forceinline__ void st_cluster_v4(uint32_t laddr, int rank, float4 v) {
    uint32_t ra;
    asm volatile("mapa.shared::cluster.u32 %0, %1, %2;" : "=r"(ra) : "r"(laddr), "r"(rank));
    asm volatile("st.shared::cluster.v4.b32 [%0], {%1,%2,%3,%4};"
                 :: "r"(ra), "r"(__float_as_uint(v.x)), "r"(__float_as_uint(v.y)),
                    "r"(__float_as_uint(v.z)), "r"(__float_as_uint(v.w)) : "memory");
}
__device__ __forceinline__ void st_cluster_b64(uint32_t laddr, int rank, ull v) {
    uint32_t ra;
    asm volatile("mapa.shared::cluster.u32 %0, %1, %2;" : "=r"(ra) : "r"(laddr), "r"(rank));
    asm volatile("st.shared::cluster.b64 [%0], %1;" :: "r"(ra), "l"(v) : "memory");
}
__device__ __forceinline__ uint32_t ctarank() {
    uint32_t r;
    asm("mov.u32 %0, %%cluster_ctarank;" : "=r"(r));
    return r;
}
#define CL_ARRIVE() asm volatile("barrier.cluster.arrive.aligned;" ::: "memory")
#define CL_WAIT()   asm volatile("barrier.cluster.wait.aligned;" ::: "memory")

// GEMV slice: ITERS k-steps (k = p + 8*i), 4 cols x 2 rows per thread.
// W from global (L2), h (plain floats, 2 rows) from smem.
template<int ITERS>
__device__ __forceinline__ void gpart(const float* __restrict__ Wp,
                                      const float* __restrict__ hp, ull* acc) {
#pragma unroll 8
    for (int i = 0; i < ITERS; ++i) {
        ulonglong2 w = *(const ulonglong2*)(Wp + (size_t)i * 8 * HH);
        float2 hv = *(const float2*)(hp + i * 8 * HP);
        ull d0 = dup2(hv.x), d1 = dup2(hv.y);
        acc[0] = ffma2(d0, w.x, acc[0]); acc[1] = ffma2(d0, w.y, acc[1]);
        acc[2] = ffma2(d1, w.x, acc[2]); acc[3] = ffma2(d1, w.y, acc[3]);
    }
}

__global__ void __launch_bounds__(NTHR, 2) __cluster_dims__(NC, 1, 1)
rnn_occ2_kernel(
    const float* __restrict__ x,
    const float* __restrict__ Wi0, const float* __restrict__ bi0,
    const float* __restrict__ Wh0, const float* __restrict__ bh0,
    const float* __restrict__ g0,  const float* __restrict__ be0,
    const float* __restrict__ Wi1, const float* __restrict__ bi1,
    const float* __restrict__ Wh1, const float* __restrict__ bh1,
    const float* __restrict__ g1,  const float* __restrict__ be1,
    const float* __restrict__ Wfc, const float* __restrict__ bfc,
    float* __restrict__ out)
{
    extern __shared__ float sm[];
    float*  h0x   = sm + OF_H0X;
    float*  h1x   = sm + OF_H1X;
    float*  red   = sm + OF_RED;
    float*  inbox = sm + OF_INBOX;
    float2* part  = (float2*)(sm + OF_PART);
    float*  sg0   = sm + OF_SG0;  float* sb0 = sm + OF_SB0;
    float*  sg1   = sm + OF_SG1;  float* sb1 = sm + OF_SB1;
    float*  cb0   = sm + OF_CB0;  float* cb1 = sm + OF_CB1;
    float2* sp    = (float2*)(sm + OF_SP);
    float*  smu   = sm + OF_SMU;  float* srs = sm + OF_SRS;

    const int tid  = threadIdx.x;
    const int lane = tid & 31;
    const int p    = tid >> 5;          // warp = k-phase (8)
    const int cgo  = (lane & 15) * 4;   // col offset (4-col group)
    const int rqo  = (lane >> 4) * 2;   // row offset (2-row pair)
    const int rank = (int)ctarank();
    const int g    = blockIdx.x >> 3;
    const int c0   = rank * CW;
    const int row0 = g * RG;

    const uint32_t inbox_b = smem_u32(inbox);
    const uint32_t part_b  = smem_u32(part);

    // epilogue constants: 1 output/thread
    const int erow = tid >> 6;          // 0..3
    const int ecol = tid & 63;          // 0..63
    const int lane_src = ((erow >> 1) << 4) | (ecol >> 2);
    const int fidx = (((erow & 1) << 1) | ((ecol >> 1) & 1)) * 2 + (ecol & 1);
    const float* rrd = red + lane_src * 10 + fidx;

    // per-thread GEMV base pointers
    const float* wp_i0 = Wi0 + c0 + (size_t)p * HH + cgo;
    const float* wp_h0 = Wh0 + c0 + (size_t)p * HH + cgo;
    const float* wp_i1 = Wi1 + c0 + (size_t)p * HH + cgo;
    const float* wp_h1 = Wh1 + c0 + (size_t)p * HH + cgo;
    const float* hx_x  = h0x + p * HP + rqo;
    const float* hx_h0 = h0x + (64 + p) * HP + rqo;
    const float* hx_h1 = h1x + p * HP + rqo;

    // ---- init ----
    sg0[tid] = g0[tid];           sb0[tid] = be0[tid];
    sg0[tid + 256] = g0[tid + 256]; sb0[tid + 256] = be0[tid + 256];
    sg1[tid] = g1[tid];           sb1[tid] = be1[tid];
    sg1[tid + 256] = g1[tid + 256]; sb1[tid + 256] = be1[tid + 256];
    if (tid < CW) {
        cb0[tid] = bi0[c0 + tid] + bh0[c0 + tid];
        cb1[tid] = bi1[c0 + tid] + bh1[c0 + tid];
    }
    for (int i = tid; i < 576 * HP; i += NTHR) h0x[i] = 0.f;
    for (int i = tid; i < 512 * HP; i += NTHR) h1x[i] = 0.f;
    __syncthreads();
    CL_ARRIVE();     // publishes init; pairs with first E1 wait

    // x staging: 4 rows x 64 k = 256 threads exactly
    const int xr = tid >> 6, xk = tid & 63;
    const float* xbase = x + (size_t)(row0 + xr) * TSTEPS * DIN + xk;
    float xreg = xbase[0];

    ull acc[4];

    for (int t = 0; t < TSTEPS; ++t) {
        h0x[xk * HP + xr] = xreg;
        __syncthreads();

        // ---- G0: x·Wi0 + h0n(t-1)·Wh0  (overlaps E1(t-1) exchange) ----
#pragma unroll
        for (int q = 0; q < 4; ++q) acc[q] = 0ull;
        gpart<8>(wp_i0, hx_x, acc);
        gpart<64>(wp_h0, hx_h0, acc);

        CL_WAIT();                       // E1(t-1): inbox[1], part[1] valid
        if (t > 0 && tid < 32) {         // LN stats for h1n(t-1)
            int r = tid >> 3, s8 = tid & 7;
            float2 pv = part[(NC + s8) * RG + r];
#pragma unroll
            for (int o = 4; o; o >>= 1) {
                pv.x += __shfl_xor_sync(0xffffffffu, pv.x, o);
                pv.y += __shfl_xor_sync(0xffffffffu, pv.y, o);
            }
            if (s8 == 0) {
                float mu = pv.x * (1.f / HH);
                float var = pv.y * (1.f / HH) - mu * mu;
                smu[r] = mu; srs[r] = rsqrtf(var + EPSF);
            }
        }
        __syncthreads();
        if (t > 0) {                     // rebuild h1n(t-1): 2 cols/thread
#pragma unroll
            for (int cc = 0; cc < 2; ++cc) {
                int c = tid + cc * 256;
                float gk = sg1[c], bk = sb1[c];
                const float* ib = inbox + RG * HH + c;
                float* hd = h1x + c * HP;
                hd[0] = (ib[0 * HH] - smu[0]) * srs[0] * gk + bk;
                hd[1] = (ib[1 * HH] - smu[1]) * srs[1] * gk + bk;
                hd[2] = (ib[2 * HH] - smu[2]) * srs[2] * gk + bk;
                hd[3] = (ib[3 * HH] - smu[3]) * srs[3] * gk + bk;
            }
        }
        {
            float* rw = red + p * 320 + lane * 10;
#pragma unroll
            for (int q = 0; q < 4; ++q) *(ull*)(rw + 2 * q) = acc[q];
        }
        __syncthreads();

        // ---- epilogue 0 ----
        {
            float z = 0.f;
#pragma unroll
            for (int i = 0; i < NW; ++i) z += rrd[i * 320];
            z += cb0[ecol];
            float cv = tanhf(z) + h0x[(64 + c0 + ecol) * HP + erow];
            inbox[erow * HH + c0 + ecol] = cv;
            float s = cv, q = cv * cv;
#pragma unroll
            for (int o = 16; o; o >>= 1) {
                s += __shfl_xor_sync(0xffffffffu, s, o);
                q += __shfl_xor_sync(0xffffffffu, q, o);
            }
            if (lane == 0) sp[p] = make_float2(s, q);   // warp p: row p>>1, half p&1
        }
        __syncthreads();
        if (tid < RG) {
            float2 a = sp[2 * tid], b = sp[2 * tid + 1];
            float2 pv = make_float2(a.x + b.x, a.y + b.y);
            part[rank * RG + tid] = pv;
            uint32_t off = (uint32_t)((rank * RG + tid) * 8);
            ull pbv = *(ull*)&pv;
#pragma unroll
            for (int d = 1; d < NC; ++d)
                st_cluster_b64(part_b + off, (rank + d) & (NC - 1), pbv);
        }
        if (tid < 64) {                  // push own 4x64 slice: 4 rows x 16 cg
            int rr = tid >> 4, cgi = tid & 15;
            int fo = rr * HH + c0 + 4 * cgi;
            float4 v = *(const float4*)(inbox + fo);
            uint32_t off = (uint32_t)(fo * 4);
#pragma unroll
            for (int d = 1; d < NC; ++d)
                st_cluster_v4(inbox_b + off, (rank + d) & (NC - 1), v);
        }
        CL_ARRIVE();                     // E0(t)

        // ---- G1a: h1n(t-1)·Wh1  (overlaps E0 exchange) ----
#pragma unroll
        for (int q = 0; q < 4; ++q) acc[q] = 0ull;
        gpart<64>(wp_h1, hx_h1, acc);

        CL_WAIT();                       // E0(t): inbox[0], part[0] valid
        if (tid < 32) {                  // LN stats for h0n(t)
            int r = tid >> 3, s8 = tid & 7;
            float2 pv = part[s8 * RG + r];
#pragma unroll
            for (int o = 4; o; o >>= 1) {
                pv.x += __shfl_xor_sync(0xffffffffu, pv.x, o);
                pv.y += __shfl_xor_sync(0xffffffffu, pv.y, o);
            }
            if (s8 == 0) {
                float mu = pv.x * (1.f / HH);
                float var = pv.y * (1.f / HH) - mu * mu;
                smu[r] = mu; srs[r] = rsqrtf(var + EPSF);
            }
        }
        __syncthreads();
        {                                // rebuild h0n(t): 2 cols/thread
#pragma unroll
            for (int cc = 0; cc < 2; ++cc) {
                int c = tid + cc * 256;
                float gk = sg0[c], bk = sb0[c];
                const float* ib = inbox + c;
                float* hd = h0x + (64 + c) * HP;
                hd[0] = (ib[0 * HH] - smu[0]) * srs[0] * gk + bk;
                hd[1] = (ib[1 * HH] - smu[1]) * srs[1] * gk + bk;
                hd[2] = (ib[2 * HH] - smu[2]) * srs[2] * gk + bk;
                hd[3] = (ib[3 * HH] - smu[3]) * srs[3] * gk + bk;
            }
        }
        __syncthreads();

        // ---- G1b: h0n(t)·Wi1 ----
        gpart<64>(wp_i1, hx_h0, acc);
        if (t + 1 < TSTEPS) xreg = xbase[(size_t)(t + 1) * DIN];
        {
            float* rw = red + p * 320 + lane * 10;
#pragma unroll
            for (int q = 0; q < 4; ++q) *(ull*)(rw + 2 * q) = acc[q];
        }
        __syncthreads();

        // ---- epilogue 1 ----
        {
            float z = 0.f;
#pragma unroll
            for (int i = 0; i < NW; ++i) z += rrd[i * 320];
            z += cb1[ecol];
            float cv = tanhf(z) + h1x[(c0 + ecol) * HP + erow];
            inbox[RG * HH + erow * HH + c0 + ecol] = cv;
            float s = cv, q = cv * cv;
#pragma unroll
            for (int o = 16; o; o >>= 1) {
                s += __shfl_xor_sync(0xffffffffu, s, o);
                q += __shfl_xor_sync(0xffffffffu, q, o);
            }
            if (lane == 0) sp[p] = make_float2(s, q);
        }
        __syncthreads();
        if (tid < RG) {
            float2 a = sp[2 * tid], b = sp[2 * tid + 1];
            float2 pv = make_float2(a.x + b.x, a.y + b.y);
            part[(NC + rank) * RG + tid] = pv;
            uint32_t off = (uint32_t)(((NC + rank) * RG + tid) * 8);
            ull pbv = *(ull*)&pv;
#pragma unroll
            for (int d = 1; d < NC; ++d)
                st_cluster_b64(part_b + off, (rank + d) & (NC - 1), pbv);
        }
        if (tid < 64) {
            int rr = tid >> 4, cgi = tid & 15;
            int fo = RG * HH + rr * HH + c0 + 4 * cgi;
            float4 v = *(const float4*)(inbox + fo);
            uint32_t off = (uint32_t)(fo * 4);
#pragma unroll
            for (int d = 1; d < NC; ++d)
                st_cluster_v4(inbox_b + off, (rank + d) & (NC - 1), v);
        }
        CL_ARRIVE();                     // E1(t)
    }

    // ---- final: wait E1(T-1), rebuild h1n, output head ----
    CL_WAIT();
    if (tid < 32) {
        int r = tid >> 3, s8 = tid & 7;
        float2 pv = part[(NC + s8) * RG + r];
#pragma unroll
        for (int o = 4; o; o >>= 1) {
            pv.x += __shfl_xor_sync(0xffffffffu, pv.x, o);
            pv.y += __shfl_xor_sync(0xffffffffu, pv.y, o);
        }
        if (s8 == 0) {
            float mu = pv.x * (1.f / HH);
            float var = pv.y * (1.f / HH) - mu * mu;
            smu[r] = mu; srs[r] = rsqrtf(var + EPSF);
        }
    }
    __syncthreads();
    {
#pragma unroll
        for (int cc = 0; cc < 2; ++cc) {
            int c = tid + cc * 256;
            float gk = sg1[c], bk = sb1[c];
            const float* ib = inbox + RG * HH + c;
            float* hd = h1x + c * HP;
#pragma unroll
            for (int r = 0; r < RG; ++r)
                hd[r] = (ib[r * HH] - smu[r]) * srs[r] * gk + bk;
        }
    }
    __syncthreads();
    if (rank == 0 && p < RG) {
        float v = 0.f;
#pragma unroll
        for (int m = 0; m < 16; ++m) {
            int k = lane + 32 * m;
            v += h1x[k * HP + p] * Wfc[k];
        }
#pragma unroll
        for (int o = 16; o; o >>= 1) v += __shfl_xor_sync(0xffffffffu, v, o);
        if (lane == 0) out[row0 + p] = v + bfc[0];
    }
}

extern "C" void kernel_launch(void* const* d_in, const int* in_sizes, int n_in,
                              void* d_out, int out_size) {
    (void)in_sizes; (void)n_in; (void)out_size;
    const float* x   = (const float*)d_in[0];
    const float* Wi0 = (const float*)d_in[1];
    const float* bi0 = (const float*)d_in[2];
    const float* Wh0 = (const float*)d_in[3];
    const float* bh0 = (const float*)d_in[4];
    const float* g0  = (const float*)d_in[5];
    const float* be0 = (const float*)d_in[6];
    const float* Wi1 = (const float*)d_in[7];
    const float* bi1 = (const float*)d_in[8];
    const float* Wh1 = (const float*)d_in[9];
    const float* bh1 = (const float*)d_in[10];
    const float* g1  = (const float*)d_in[11];
    const float* be1 = (const float*)d_in[12];
    const float* Wfc = (const float*)d_in[13];
    const float* bfc = (const float*)d_in[14];

    static int inited = 0;
    if (!inited) {
        cudaFuncSetAttribute(rnn_occ2_kernel,
                             cudaFuncAttributeMaxDynamicSharedMemorySize, SMEM_BYTES);
        inited = 1;
    }
    rnn_occ2_kernel<<<NGRP * NC, NTHR, SMEM_BYTES>>>(
        x, Wi0, bi0, Wh0, bh0, g0, be0,
        Wi1, bi1, Wh1, bh1, g1, be1,
        Wfc, bfc, (float*)d_out);
}